// round 4
// baseline (speedup 1.0000x reference)
#include <cuda_runtime.h>
#include <math.h>

// Fixed shapes: xs/hat_xs are (16, 65536, 3) float32 -> 1,048,576 vectors, 65,536 groups of 16.
#define NGROUPS      65536
#define GPB          64                     // groups per block
#define THREADS      256                    // 4 threads per group in phase A
#define NBLOCKS      (NGROUPS / GPB)        // 1024
#define PAIRS_MASK   2047
#define N0_DROP      5
#define DT           0.01f
#define INV_HUBER    200.0f
#define AOE_COEF     (0.2 / 65536.0)
#define HUB_COEF     (1.25 / 98064.0)       // 0.1*W*HUBER^2/2 / (16*2043*3)

__device__ double g_aoe = 0.0;
__device__ double g_hub = 0.0;
__device__ unsigned int g_done = 0;

// q = (x,y,z,w), w scalar. Hamilton product (R(a)R(b)).
__device__ __forceinline__ float4 qmul(float4 a, float4 b) {
    float4 r;
    r.w = a.w * b.w - a.x * b.x - a.y * b.y - a.z * b.z;
    r.x = a.w * b.x + a.x * b.w + a.y * b.z - a.z * b.y;
    r.y = a.w * b.y - a.x * b.z + a.y * b.w + a.z * b.x;
    r.z = a.w * b.z + a.x * b.y - a.y * b.x + a.z * b.w;
    return r;
}

// conj(a) * b
__device__ __forceinline__ float4 qcmul(float4 a, float4 b) {
    float4 r;
    r.w = a.w * b.w + a.x * b.x + a.y * b.y + a.z * b.z;
    r.x = a.w * b.x - a.x * b.w - a.y * b.z + a.z * b.y;
    r.y = a.w * b.y + a.x * b.z - a.y * b.w - a.z * b.x;
    r.z = a.w * b.z - a.x * b.y + a.y * b.x - a.z * b.w;
    return r;
}

// exp of small rotation vector (|v| <= ~0.1), Taylor in (a/2)^2, err ~1e-12
__device__ __forceinline__ float4 qexp_small(float x, float y, float z) {
    float a2 = fmaf(x, x, fmaf(y, y, z * z));
    float t2 = 0.25f * a2;
    float w  = fmaf(t2, fmaf(t2, (1.0f / 24.0f), -0.5f), 1.0f);           // cos(a/2)
    float k  = fmaf(t2, fmaf(t2, (0.5f / 120.0f), -(0.5f / 6.0f)), 0.5f); // sin(a/2)/a
    return make_float4(k * x, k * y, k * z, w);
}

// full-range exp (for X = exp(xs))
__device__ __forceinline__ float4 qexp_full(float x, float y, float z) {
    float a2 = fmaf(x, x, fmaf(y, y, z * z));
    float a  = sqrtf(fmaxf(a2, 1e-16f));
    float s, c;
    sincosf(0.5f * a, &s, &c);
    float k = s / a;
    if (a2 < 1e-8f) k = 0.5f;
    return make_float4(k * x, k * y, k * z, c);
}

__device__ __forceinline__ float huber_elem(float r) {
    float ar = fabsf(r);
    return (ar < 1.0f) ? 0.5f * r * r : ar - 0.5f;
}

__global__ __launch_bounds__(THREADS)
void loss_kernel(const float* __restrict__ xs, const float* __restrict__ hat,
                 float* __restrict__ out) {
    __shared__ float4 s_h[THREADS];     // per-thread partial products H
    __shared__ float  s_aoe[2], s_hub[2];
    __shared__ bool   s_last;

    const int tid = threadIdx.x;
    const int t   = tid & 3;
    const int gb  = tid >> 2;                        // group within block
    const int n   = blockIdx.x * GPB + gb;           // global group (phase A view)

    // ================= Phase A: all 256 threads, no divergence =================
    {
        const float4* hp = reinterpret_cast<const float4*>(hat) + (size_t)n * 12 + t * 3;
        float4 v0 = hp[0], v1 = hp[1], v2 = hp[2];
        float4 qa = qexp_small(DT * v0.x, DT * v0.y, DT * v0.z);
        float4 qb = qexp_small(DT * v0.w, DT * v1.x, DT * v1.y);
        float4 qc = qexp_small(DT * v1.z, DT * v1.w, DT * v2.x);
        float4 qd = qexp_small(DT * v2.y, DT * v2.z, DT * v2.w);
        s_h[tid] = qmul(qmul(qa, qb), qmul(qc, qd));
    }
    __syncthreads();

    // ================= Phase B: warps 0-1, one lane per group ==================
    float aoe = 0.0f, hub = 0.0f;
    if (tid < GPB) {
        const int g  = tid;                          // group within block
        const int ng = blockIdx.x * GPB + g;         // global group

        float4 h0 = s_h[4 * g], h1 = s_h[4 * g + 1], h2 = s_h[4 * g + 2], h3 = s_h[4 * g + 3];
        float4 Om = qmul(qmul(h0, h1), qmul(h2, h3));

        float4 xv = reinterpret_cast<const float4*>(xs)[(size_t)ng * 12];
        float4 X  = qexp_full(xv.x, xv.y, xv.z);

        // AOE: angle = 2*acos(|<qOm,qX>|), full lane utilization
        float d  = fmaf(Om.w, X.w, fmaf(Om.x, X.x, fmaf(Om.y, X.y, Om.z * X.z)));
        float ch = fminf(fabsf(d), 1.0f);
        float ang = 2.0f * acosf(ch);
        aoe = ang * ang;

        // pyramid level: pair (2m, 2m+1) = adjacent lanes
        float4 Omo, Xo;
        Omo.x = __shfl_down_sync(0xffffffffu, Om.x, 1);
        Omo.y = __shfl_down_sync(0xffffffffu, Om.y, 1);
        Omo.z = __shfl_down_sync(0xffffffffu, Om.z, 1);
        Omo.w = __shfl_down_sync(0xffffffffu, Om.w, 1);
        Xo.x  = __shfl_down_sync(0xffffffffu, X.x, 1);
        Xo.y  = __shfl_down_sync(0xffffffffu, X.y, 1);
        Xo.z  = __shfl_down_sync(0xffffffffu, X.z, 1);
        Xo.w  = __shfl_down_sync(0xffffffffu, X.w, 1);

        if ((ng & 1) == 0) {
            int m = ng >> 1;
            if ((m & PAIRS_MASK) >= N0_DROP) {
                float4 Op  = qmul(Om, Omo);
                float4 Xp  = qmul(X, Xo);
                float4 rel = qcmul(Op, Xp);          // Op^T * Xp
                float w  = rel.w;
                float ct = fminf(fmaxf(fmaf(2.0f * w, w, -1.0f), -1.0f), 1.0f);
                float an = acosf(ct);
                float sv = sqrtf(fmaxf(1.0f - w * w, 0.0f));
                float st = 2.0f * fabsf(w) * sv;     // sin(theta)
                float factor = (st < 1e-6f) ? 0.5f : an / (2.0f * st);
                float fh = factor * 4.0f * w * INV_HUBER;
                hub = huber_elem(fh * rel.x) + huber_elem(fh * rel.y) + huber_elem(fh * rel.z);
            }
        }

        // warp reduction (2 phase-B warps)
#pragma unroll
        for (int o = 16; o > 0; o >>= 1) {
            aoe += __shfl_xor_sync(0xffffffffu, aoe, o);
            hub += __shfl_xor_sync(0xffffffffu, hub, o);
        }
        if ((tid & 31) == 0) { s_aoe[tid >> 5] = aoe; s_hub[tid >> 5] = hub; }
    }
    __syncthreads();

    // ================= block total + global accumulate =================
    if (tid == 0) {
        atomicAdd(&g_aoe, (double)(s_aoe[0] + s_aoe[1]));
        atomicAdd(&g_hub, (double)(s_hub[0] + s_hub[1]));
        __threadfence();
        unsigned int old = atomicAdd(&g_done, 1u);
        s_last = (old == (unsigned int)(gridDim.x - 1));
    }
    __syncthreads();

    if (tid == 0 && s_last) {
        double aoe_t = atomicAdd(&g_aoe, 0.0);
        double hub_t = atomicAdd(&g_hub, 0.0);
        out[0] = (float)(AOE_COEF * aoe_t + HUB_COEF * hub_t);
        g_aoe = 0.0;
        g_hub = 0.0;
        __threadfence();
        atomicExch(&g_done, 0u);
    }
}

extern "C" void kernel_launch(void* const* d_in, const int* in_sizes, int n_in,
                              void* d_out, int out_size) {
    const float* xs  = (const float*)d_in[0];
    const float* hat = (const float*)d_in[1];
    (void)in_sizes; (void)n_in; (void)out_size;
    loss_kernel<<<NBLOCKS, THREADS>>>(xs, hat, (float*)d_out);
}

// round 5
// speedup vs baseline: 1.1281x; 1.1281x over previous
#include <cuda_runtime.h>
#include <math.h>

// Fixed shapes: xs/hat_xs are (16, 65536, 3) float32 -> 1,048,576 vectors, 65,536 groups of 16.
#define NGROUPS      65536
#define GPB          64                     // groups per block
#define THREADS      256                    // 4 threads per group in phase A
#define NBLOCKS      (NGROUPS / GPB)        // 1024
#define PAIRS_MASK   2047
#define N0_DROP      5
#define DT           0.01f
#define INV_HUBER    200.0f
#define AOE_COEF     (0.2 / 65536.0)
#define HUB_COEF     (1.25 / 98064.0)       // 0.1*W*HUBER^2/2 / (16*2043*3)

__device__ float2 g_part[NBLOCKS];          // per-block partials (no atomics)

// q = (x,y,z,w), w scalar. Hamilton product (R(a)R(b)).
__device__ __forceinline__ float4 qmul(float4 a, float4 b) {
    float4 r;
    r.w = a.w * b.w - a.x * b.x - a.y * b.y - a.z * b.z;
    r.x = a.w * b.x + a.x * b.w + a.y * b.z - a.z * b.y;
    r.y = a.w * b.y - a.x * b.z + a.y * b.w + a.z * b.x;
    r.z = a.w * b.z + a.x * b.y - a.y * b.x + a.z * b.w;
    return r;
}

// conj(a) * b
__device__ __forceinline__ float4 qcmul(float4 a, float4 b) {
    float4 r;
    r.w = a.w * b.w + a.x * b.x + a.y * b.y + a.z * b.z;
    r.x = a.w * b.x - a.x * b.w - a.y * b.z + a.z * b.y;
    r.y = a.w * b.y + a.x * b.z - a.y * b.w - a.z * b.x;
    r.z = a.w * b.z - a.x * b.y + a.y * b.x - a.z * b.w;
    return r;
}

// exp of small rotation vector (|v| <= ~0.1), Taylor in (a/2)^2, err ~1e-12
__device__ __forceinline__ float4 qexp_small(float x, float y, float z) {
    float a2 = fmaf(x, x, fmaf(y, y, z * z));
    float t2 = 0.25f * a2;
    float w  = fmaf(t2, fmaf(t2, (1.0f / 24.0f), -0.5f), 1.0f);           // cos(a/2)
    float k  = fmaf(t2, fmaf(t2, (0.5f / 120.0f), -(0.5f / 6.0f)), 0.5f); // sin(a/2)/a
    return make_float4(k * x, k * y, k * z, w);
}

// full-range exp (for X = exp(xs))
__device__ __forceinline__ float4 qexp_full(float x, float y, float z) {
    float a2 = fmaf(x, x, fmaf(y, y, z * z));
    float a  = sqrtf(fmaxf(a2, 1e-16f));
    float s, c;
    sincosf(0.5f * a, &s, &c);
    float k = s / a;
    if (a2 < 1e-8f) k = 0.5f;
    return make_float4(k * x, k * y, k * z, c);
}

__device__ __forceinline__ float huber_elem(float r) {
    float ar = fabsf(r);
    return (ar < 1.0f) ? 0.5f * r * r : ar - 0.5f;
}

__global__ __launch_bounds__(THREADS)
void loss_kernel(const float* __restrict__ xs, const float* __restrict__ hat) {
    __shared__ float4 s_h[THREADS];     // per-thread partial products H
    __shared__ float  s_aoe[2], s_hub[2];

    const int tid = threadIdx.x;
    const int t   = tid & 3;
    const int gb  = tid >> 2;                        // group within block
    const int n   = blockIdx.x * GPB + gb;           // global group (phase A view)

    // ================= Phase A: all 256 threads, no divergence =================
    {
        const float4* hp = reinterpret_cast<const float4*>(hat) + (size_t)n * 12 + t * 3;
        float4 v0 = hp[0], v1 = hp[1], v2 = hp[2];
        float4 qa = qexp_small(DT * v0.x, DT * v0.y, DT * v0.z);
        float4 qb = qexp_small(DT * v0.w, DT * v1.x, DT * v1.y);
        float4 qc = qexp_small(DT * v1.z, DT * v1.w, DT * v2.x);
        float4 qd = qexp_small(DT * v2.y, DT * v2.z, DT * v2.w);
        s_h[tid] = qmul(qmul(qa, qb), qmul(qc, qd));
    }
    __syncthreads();

    // ================= Phase B: warps 0-1, one lane per group ==================
    if (tid < GPB) {
        const int g  = tid;
        const int ng = blockIdx.x * GPB + g;

        float4 h0 = s_h[4 * g], h1 = s_h[4 * g + 1], h2 = s_h[4 * g + 2], h3 = s_h[4 * g + 3];
        float4 Om = qmul(qmul(h0, h1), qmul(h2, h3));

        float4 xv = reinterpret_cast<const float4*>(xs)[(size_t)ng * 12];
        float4 X  = qexp_full(xv.x, xv.y, xv.z);

        // AOE: angle = 2*acos(|<qOm,qX>|)
        float d  = fmaf(Om.w, X.w, fmaf(Om.x, X.x, fmaf(Om.y, X.y, Om.z * X.z)));
        float ch = fminf(fabsf(d), 1.0f);
        float ang = 2.0f * acosf(ch);
        float aoe = ang * ang;
        float hub = 0.0f;

        // pyramid level: pair (2m, 2m+1) = adjacent lanes
        float4 Omo, Xo;
        Omo.x = __shfl_down_sync(0xffffffffu, Om.x, 1);
        Omo.y = __shfl_down_sync(0xffffffffu, Om.y, 1);
        Omo.z = __shfl_down_sync(0xffffffffu, Om.z, 1);
        Omo.w = __shfl_down_sync(0xffffffffu, Om.w, 1);
        Xo.x  = __shfl_down_sync(0xffffffffu, X.x, 1);
        Xo.y  = __shfl_down_sync(0xffffffffu, X.y, 1);
        Xo.z  = __shfl_down_sync(0xffffffffu, X.z, 1);
        Xo.w  = __shfl_down_sync(0xffffffffu, X.w, 1);

        if ((ng & 1) == 0) {
            int m = ng >> 1;
            if ((m & PAIRS_MASK) >= N0_DROP) {
                float4 Op  = qmul(Om, Omo);
                float4 Xp  = qmul(X, Xo);
                float4 rel = qcmul(Op, Xp);          // Op^T * Xp
                float w  = rel.w;
                float ct = fminf(fmaxf(fmaf(2.0f * w, w, -1.0f), -1.0f), 1.0f);
                float an = acosf(ct);
                float sv = sqrtf(fmaxf(1.0f - w * w, 0.0f));
                float st = 2.0f * fabsf(w) * sv;     // sin(theta)
                float factor = (st < 1e-6f) ? 0.5f : an / (2.0f * st);
                float fh = factor * 4.0f * w * INV_HUBER;
                hub = huber_elem(fh * rel.x) + huber_elem(fh * rel.y) + huber_elem(fh * rel.z);
            }
        }

#pragma unroll
        for (int o = 16; o > 0; o >>= 1) {
            aoe += __shfl_xor_sync(0xffffffffu, aoe, o);
            hub += __shfl_xor_sync(0xffffffffu, hub, o);
        }
        if ((tid & 31) == 0) { s_aoe[tid >> 5] = aoe; s_hub[tid >> 5] = hub; }
    }
    __syncthreads();

    // ---- plain store of per-block partial (no atomics, no fences, no counter)
    if (tid == 0)
        g_part[blockIdx.x] = make_float2(s_aoe[0] + s_aoe[1], s_hub[0] + s_hub[1]);
}

// Final reduction: 1 block, 256 threads, 1024 float2 = 8KB coalesced.
__global__ __launch_bounds__(256)
void reduce_kernel(float* __restrict__ out) {
    const int tid = threadIdx.x;
    double aoe = 0.0, hub = 0.0;
#pragma unroll
    for (int i = 0; i < NBLOCKS / 256; i++) {
        float2 p = g_part[tid + i * 256];
        aoe += (double)p.x;
        hub += (double)p.y;
    }
#pragma unroll
    for (int o = 16; o > 0; o >>= 1) {
        aoe += __shfl_xor_sync(0xffffffffu, aoe, o);
        hub += __shfl_xor_sync(0xffffffffu, hub, o);
    }
    __shared__ double s_a[8], s_b[8];
    if ((tid & 31) == 0) { s_a[tid >> 5] = aoe; s_b[tid >> 5] = hub; }
    __syncthreads();
    if (tid == 0) {
        double ta = 0.0, tb = 0.0;
#pragma unroll
        for (int i = 0; i < 8; i++) { ta += s_a[i]; tb += s_b[i]; }
        out[0] = (float)(AOE_COEF * ta + HUB_COEF * tb);
    }
}

extern "C" void kernel_launch(void* const* d_in, const int* in_sizes, int n_in,
                              void* d_out, int out_size) {
    const float* xs  = (const float*)d_in[0];
    const float* hat = (const float*)d_in[1];
    (void)in_sizes; (void)n_in; (void)out_size;
    loss_kernel<<<NBLOCKS, THREADS>>>(xs, hat);
    reduce_kernel<<<1, 256>>>((float*)d_out);
}